// round 9
// baseline (speedup 1.0000x reference)
#include <cuda_runtime.h>
#include <cuda_bf16.h>
#include <math.h>
#include <stdint.h>

#define BB   256
#define TT   365
#define HH   512
#define DD   32
#define K3   1536
#define DS   27
#define NBLK 128
#define KTOT 544

// ---------------- persistent device state ----------------
// Weight staging: row P = nt*96 + g*32 + ul, k in [0,544) = [x(32) ; h(512)]
__device__ __align__(16) __nv_bfloat16 g_Wp_hi[K3 * KTOT];
__device__ __align__(16) __nv_bfloat16 g_Wp_lo[K3 * KTOT];
__device__ __align__(16) __nv_bfloat16 g_x_hi[BB * TT * DD];
__device__ __align__(16) __nv_bfloat16 g_x_lo[BB * TT * DD];
__device__ __align__(16) __nv_bfloat16 g_h_hi[2][BB * HH];
__device__ __align__(16) __nv_bfloat16 g_h_lo[2][BB * HH];
__device__ unsigned g_ready[8 * 16 * 32];      // flag per (mt,nt), 128B stride

__device__ __forceinline__ float hsig(float x) {
    return fminf(fmaxf(0.2f * x + 0.5f, 0.0f), 1.0f);
}
__device__ __forceinline__ float ftanh(float x) {
    float t = __expf(-2.0f * fabsf(x));
    return copysignf(__fdividef(1.0f - t, 1.0f + t), x);
}
__device__ __forceinline__ uint32_t smem_u32(const void* p) {
    uint32_t a;
    asm("{ .reg .u64 t; cvta.to.shared.u64 t, %1; cvt.u32.u64 %0, t; }" : "=r"(a) : "l"(p));
    return a;
}
__device__ __forceinline__ unsigned ldacq(const unsigned* p) {
    unsigned v;
    asm volatile("ld.acquire.gpu.global.u32 %0, [%1];" : "=r"(v) : "l"(p) : "memory");
    return v;
}
__device__ __forceinline__ void strel(unsigned* p, unsigned v) {
    asm volatile("st.release.gpu.global.u32 [%0], %1;" :: "l"(p), "r"(v) : "memory");
}

#define LDSM_X4(r0, r1, r2, r3, addr)                                          \
    asm volatile("ldmatrix.sync.aligned.m8n8.x4.shared.b16 {%0,%1,%2,%3}, [%4];" \
                 : "=r"(r0), "=r"(r1), "=r"(r2), "=r"(r3) : "r"(addr))

#define MMA_BF16(d, a0, a1, a2, a3, b0, b1)                                    \
    asm volatile("mma.sync.aligned.m16n8k16.row.col.f32.bf16.bf16.f32 "        \
                 "{%0,%1,%2,%3}, {%4,%5,%6,%7}, {%8,%9}, {%0,%1,%2,%3};"       \
                 : "+f"((d)[0]), "+f"((d)[1]), "+f"((d)[2]), "+f"((d)[3])      \
                 : "r"(a0), "r"(a1), "r"(a2), "r"(a3), "r"(b0), "r"(b1))

#define CP_ASYNC(dst, src, sz) \
    asm volatile("cp.async.cg.shared.global [%0], [%1], 16, %2;" \
                 :: "r"(dst), "l"(src), "r"(sz))
#define CP_COMMIT() asm volatile("cp.async.commit_group;" ::: "memory")
#define CP_WAIT0()  asm volatile("cp.async.wait_group 0;" ::: "memory")
#define CP_WAIT1()  asm volatile("cp.async.wait_group 1;" ::: "memory")

// ---------------- SMEM layout ----------------
#define BROW      1104            // 544*2 + 16B pad
#define SM_BHI    0
#define SM_BLO    105984
#define SM_A      211968          // 2 bufs x (hi 4608 + lo 4608); also reduction area
#define ABUF_SZ   9216
#define SMEM_TOTAL 230400

// ---------------- prep kernels ----------------
__global__ void reset_flags() {
    int i = blockIdx.x * blockDim.x + threadIdx.x;
    if (i < 8 * 16 * 32) g_ready[i] = 0;
}

__global__ void prep_weights(const float* __restrict__ Wx, const float* __restrict__ Wh) {
    int P = blockIdx.x;                 // P = nt*96 + g*32 + ul
    int nt = P / 96, rq = P - nt * 96;
    int g = rq >> 5, ul = rq & 31;
    int col = g * HH + nt * 32 + ul;
    for (int k = threadIdx.x; k < KTOT; k += blockDim.x) {
        float w = (k < DD) ? Wx[(size_t)k * K3 + col]
                           : Wh[(size_t)(k - DD) * K3 + col];
        __nv_bfloat16 hi = __float2bfloat16(w);
        g_Wp_hi[(size_t)P * KTOT + k] = hi;
        g_Wp_lo[(size_t)P * KTOT + k] = __float2bfloat16(w - __bfloat162float(hi));
    }
}

__global__ void prep_x(const float* __restrict__ x_dyn) {
    int i = blockIdx.x * blockDim.x + threadIdx.x;
    if (i >= BB * TT * DD) return;
    float v = x_dyn[i];
    __nv_bfloat16 hi = __float2bfloat16(v);
    g_x_hi[i] = hi;
    g_x_lo[i] = __float2bfloat16(v - __bfloat162float(hi));
}

// ---------------- A-chunk loader, rotated block order ----------------
// chunk i: sub-block 0 = (i==0 ? x : h-block), sub-block 1 = h-block / zfill
__device__ __forceinline__ void issue_chunk(int i, int t, int m0, int nt,
                                            uint32_t abase,
                                            const __nv_bfloat16* __restrict__ hhi,
                                            const __nv_bfloat16* __restrict__ hlo,
                                            int tid) {
#pragma unroll
    for (int n = 0; n < 2; n++) {
        int idx = tid + n * 256;
        int half = idx >> 8;            // 0 hi, 1 lo
        int rem = idx & 255;
        int rr = rem >> 3, q = rem & 7;
        int s = q >> 2, qq = q & 3;
        uint32_t dst = abase + half * 4608 + rr * 144 + q * 16;
        const __nv_bfloat16* src;
        int sz = 16;
        if (i == 0 && s == 0) {
            src = (half ? g_x_lo : g_x_hi) + ((size_t)(m0 + rr) * TT + t) * DD + qq * 8;
        } else {
            int b;
            if (i == 0)      b = nt;
            else if (i == 8) { b = (nt + 15) & 15; if (s == 1) sz = 0; }
            else             b = (nt + 2 * i - 1 + s) & 15;
            src = (half ? hlo : hhi) + (size_t)(m0 + rr) * HH + b * 32 + qq * 8;
        }
        CP_ASYNC(dst, src, sz);
    }
    CP_COMMIT();
}

// ---------------- persistent LSTM kernel ----------------
// 128 CTAs x 256 thr. CTA tile 32 rows x 32 units (96 z-cols).
// Warp tile 32m x 8u x 3g; warps w and w+4 split k, reduced via smem.
// Sync: per-producer epoch flags (no global barrier).
__global__ __launch_bounds__(256, 1)
void lstm_persist(const float* __restrict__ x_static,
                  const float* __restrict__ sk,
                  const float* __restrict__ sb,
                  const float* __restrict__ bias,
                  float* __restrict__ out) {
    extern __shared__ char smem[];
    const uint32_t s0 = smem_u32(smem);
    const int tid = threadIdx.x;
    const int lane = tid & 31;
    const int wid = tid >> 5;
    const int nq = wid & 3;
    const int khalf = wid >> 2;
    const int mt = blockIdx.x & 7;
    const int nt = blockIdx.x >> 3;
    const int m0 = mt * 32;
    const int u0 = nt * 32;
    unsigned* const myflag = g_ready + (mt * 16 + nt) * 32;

    // ---- one-time: weights into SMEM ----
    for (int i = tid; i < 96 * 68; i += 256) {
        int pl = i / 68, c = i - pl * 68;
        size_t src = (size_t)(nt * 96 + pl) * KTOT + c * 8;
        *reinterpret_cast<uint4*>(smem + SM_BHI + pl * BROW + c * 16) =
            *reinterpret_cast<const uint4*>(&g_Wp_hi[src]);
        *reinterpret_cast<uint4*>(smem + SM_BLO + pl * BROW + c * 16) =
            *reinterpret_cast<const uint4*>(&g_Wp_lo[src]);
    }

    // ---- per-thread ownership (epilogue in khalf==0 warps) ----
    const int gr = m0 + (lane >> 2);
    const int uA = u0 + nq * 8 + (lane & 3) * 2;

    const float bf0 = bias[uA],          bf1 = bias[uA + 1];
    const float bg0 = bias[HH + uA],     bg1 = bias[HH + uA + 1];
    const float bo0 = bias[2 * HH + uA], bo1 = bias[2 * HH + uA + 1];

    float c_reg[8], ig_reg[8];
#pragma unroll
    for (int i = 0; i < 8; i++) c_reg[i] = 0.f;
    if (khalf == 0) {
#pragma unroll
        for (int i = 0; i < 4; i++) {
            int row = gr + i * 8;
#pragma unroll
            for (int jj = 0; jj < 2; jj++) {
                int u = uA + jj;
                float a = sb[u];
#pragma unroll
                for (int d = 0; d < DS; d++)
                    a = fmaf(x_static[row * DS + d], sk[d * HH + u], a);
                ig_reg[i * 2 + jj] = hsig(a);
            }
            __nv_bfloat162 z2; z2.x = __float2bfloat16(0.f); z2.y = z2.x;
            *reinterpret_cast<__nv_bfloat162*>(&g_h_hi[0][row * HH + uA]) = z2;
            *reinterpret_cast<__nv_bfloat162*>(&g_h_lo[0][row * HH + uA]) = z2;
        }
    }
    __threadfence();
    __syncthreads();
    if (tid == 0) strel(myflag, 1u);    // h(0) published

    // ---- ldmatrix lane addresses ----
    const uint32_t a_off = (lane & 15) * 144 + (lane >> 4) * 16;
    const int oct = lane >> 3, l8 = lane & 7;
    const uint32_t koff = (oct & 1) * 16;
    const int wq8 = nq * 8;
    const uint32_t bA = s0 + SM_BHI + ((oct < 2 ? wq8 : 32 + wq8) + l8) * BROW + koff;
    const uint32_t bB = (oct < 2 ? s0 + SM_BHI + (64 + wq8 + l8) * BROW
                                 : s0 + SM_BLO + (wq8 + l8) * BROW) + koff;
    const uint32_t bC = s0 + SM_BLO + ((oct < 2 ? 32 : 64) + wq8 + l8) * BROW + koff;

    const unsigned* pf1 = myflag;
    const unsigned* pf2 = myflag;
    unsigned v1 = 0, v2 = 0;

#pragma unroll 1
    for (int t = 0; t < TT; t++) {
        const int tpar = t & 1;
        const unsigned e = (unsigned)t + 1u;
        const __nv_bfloat16* __restrict__ hhi = g_h_hi[tpar];
        const __nv_bfloat16* __restrict__ hlo = g_h_lo[tpar];

        float acc[3][2][4];
#pragma unroll
        for (int g = 0; g < 3; g++)
#pragma unroll
            for (int mf = 0; mf < 2; mf++)
#pragma unroll
                for (int e2 = 0; e2 < 4; e2++) acc[g][mf][e2] = 0.f;

        // preload flags for chunk 1 producers
        {
            int a1 = (nt + 1) & 15, a2 = (nt + 2) & 15;
            pf1 = g_ready + (mt * 16 + a1) * 32;
            pf2 = g_ready + (mt * 16 + a2) * 32;
            v1 = ldacq(pf1); v2 = ldacq(pf2);
        }
        issue_chunk(0, t, m0, nt, s0 + SM_A, hhi, hlo, tid);

#pragma unroll 1
        for (int i = 0; i < 9; i++) {
            if (i > 0) __syncthreads();
            if (i < 8) {
                // gate chunk i+1 on its producers (values preloaded earlier)
                if (v1 < e || v2 < e) {
                    do { v1 = ldacq(pf1); v2 = ldacq(pf2); } while (v1 < e || v2 < e);
                }
                issue_chunk(i + 1, t, m0, nt, s0 + SM_A + ((i + 1) & 1) * ABUF_SZ,
                            hhi, hlo, tid);
                if (i < 7) {                 // preload flags for chunk i+2
                    int j = i + 2;
                    int a1 = (j == 8) ? ((nt + 15) & 15) : ((nt + 2 * j - 1) & 15);
                    int a2 = (j == 8) ? a1 : ((nt + 2 * j) & 15);
                    pf1 = g_ready + (mt * 16 + a1) * 32;
                    pf2 = g_ready + (mt * 16 + a2) * 32;
                    v1 = ldacq(pf1); v2 = ldacq(pf2);
                }
                CP_WAIT1();
            } else {
                CP_WAIT0();
            }
            __syncthreads();

            const uint32_t Abuf = s0 + SM_A + (i & 1) * ABUF_SZ + a_off;
            // this warp's sub-block and weight k-offset
            int bblk;
            uint32_t Boff;
            if (i == 0)      { bblk = nt; Boff = (khalf == 0) ? 0u : (uint32_t)(2 + 2 * bblk) * 32; }
            else if (i == 8) { bblk = (nt + 15) & 15; Boff = (uint32_t)(2 + 2 * bblk) * 32; }
            else             { bblk = (nt + 2 * i - 1 + khalf) & 15; Boff = (uint32_t)(2 + 2 * bblk) * 32; }
            const uint32_t aSub = (i < 8) ? (uint32_t)khalf * 64 : 0u;
            const int ks0 = (i < 8) ? 0 : khalf;
            const int nks = (i < 8) ? 2 : 1;

            for (int ii = 0; ii < nks; ii++) {
                const int ks = ks0 + ii;
                const uint32_t Ab = Abuf + aSub + ks * 32;
                const uint32_t Bb = Boff + ks * 32;
                uint32_t ah0, ah1, ah2, ah3, ai0, ai1, ai2, ai3;
                uint32_t al0, al1, al2, al3, am0, am1, am2, am3;
                uint32_t p0, p1, p2, p3, q0, q1, q2, q3, r0, r1, r2, r3;
                LDSM_X4(ah0, ah1, ah2, ah3, Ab);
                LDSM_X4(ai0, ai1, ai2, ai3, Ab + 16 * 144);
                LDSM_X4(al0, al1, al2, al3, Ab + 4608);
                LDSM_X4(am0, am1, am2, am3, Ab + 4608 + 16 * 144);
                LDSM_X4(p0, p1, p2, p3, bA + Bb);
                LDSM_X4(q0, q1, q2, q3, bB + Bb);
                LDSM_X4(r0, r1, r2, r3, bC + Bb);
                // hi x hi
                MMA_BF16(acc[0][0], ah0, ah1, ah2, ah3, p0, p1);
                MMA_BF16(acc[0][1], ai0, ai1, ai2, ai3, p0, p1);
                MMA_BF16(acc[1][0], ah0, ah1, ah2, ah3, p2, p3);
                MMA_BF16(acc[1][1], ai0, ai1, ai2, ai3, p2, p3);
                MMA_BF16(acc[2][0], ah0, ah1, ah2, ah3, q0, q1);
                MMA_BF16(acc[2][1], ai0, ai1, ai2, ai3, q0, q1);
                // hi x lo (weight lo)
                MMA_BF16(acc[0][0], ah0, ah1, ah2, ah3, q2, q3);
                MMA_BF16(acc[0][1], ai0, ai1, ai2, ai3, q2, q3);
                MMA_BF16(acc[1][0], ah0, ah1, ah2, ah3, r0, r1);
                MMA_BF16(acc[1][1], ai0, ai1, ai2, ai3, r0, r1);
                MMA_BF16(acc[2][0], ah0, ah1, ah2, ah3, r2, r3);
                MMA_BF16(acc[2][1], ai0, ai1, ai2, ai3, r2, r3);
                // lo x hi (activation lo)
                MMA_BF16(acc[0][0], al0, al1, al2, al3, p0, p1);
                MMA_BF16(acc[0][1], am0, am1, am2, am3, p0, p1);
                MMA_BF16(acc[1][0], al0, al1, al2, al3, p2, p3);
                MMA_BF16(acc[1][1], am0, am1, am2, am3, p2, p3);
                MMA_BF16(acc[2][0], al0, al1, al2, al3, q0, q1);
                MMA_BF16(acc[2][1], am0, am1, am2, am3, q0, q1);
            }
        }

        // ---- cross-warp k reduction via smem ----
        __syncthreads();
        float* red = reinterpret_cast<float*>(smem + SM_A);
        if (khalf == 1) {
            int s = (wid - 4) * 32 + lane;
#pragma unroll
            for (int g = 0; g < 3; g++)
#pragma unroll
                for (int mf = 0; mf < 2; mf++)
#pragma unroll
                    for (int e2 = 0; e2 < 4; e2++)
                        red[(g * 8 + mf * 4 + e2) * 128 + s] = acc[g][mf][e2];
        }
        __syncthreads();

        if (khalf == 0) {
            int s = wid * 32 + lane;
#pragma unroll
            for (int g = 0; g < 3; g++)
#pragma unroll
                for (int mf = 0; mf < 2; mf++)
#pragma unroll
                    for (int e2 = 0; e2 < 4; e2++)
                        acc[g][mf][e2] += red[(g * 8 + mf * 4 + e2) * 128 + s];

            __nv_bfloat16* __restrict__ hdst_hi = g_h_hi[tpar ^ 1];
            __nv_bfloat16* __restrict__ hdst_lo = g_h_lo[tpar ^ 1];
#pragma unroll
            for (int i = 0; i < 4; i++) {
                const int mf = i >> 1, dp = (i & 1) * 2;
                float zf0 = acc[0][mf][dp + 0] + bf0, zf1 = acc[0][mf][dp + 1] + bf1;
                float zg0 = acc[1][mf][dp + 0] + bg0, zg1 = acc[1][mf][dp + 1] + bg1;
                float zo0 = acc[2][mf][dp + 0] + bo0, zo1 = acc[2][mf][dp + 1] + bo1;
                float c0 = hsig(zf0) * c_reg[i * 2 + 0] + ig_reg[i * 2 + 0] * ftanh(zg0);
                float c1 = hsig(zf1) * c_reg[i * 2 + 1] + ig_reg[i * 2 + 1] * ftanh(zg1);
                c_reg[i * 2 + 0] = c0;
                c_reg[i * 2 + 1] = c1;
                float h0 = hsig(zo0) * ftanh(c0);
                float h1 = hsig(zo1) * ftanh(c1);
                int row = gr + i * 8;
                int idx = row * HH + uA;
                __nv_bfloat16 b0 = __float2bfloat16(h0);
                __nv_bfloat16 b1 = __float2bfloat16(h1);
                __nv_bfloat162 ph; ph.x = b0; ph.y = b1;
                *reinterpret_cast<__nv_bfloat162*>(&hdst_hi[idx]) = ph;
                __nv_bfloat162 pl;
                pl.x = __float2bfloat16(h0 - __bfloat162float(b0));
                pl.y = __float2bfloat16(h1 - __bfloat162float(b1));
                *reinterpret_cast<__nv_bfloat162*>(&hdst_lo[idx]) = pl;
                float2 ov = make_float2(h0, h1);
                *reinterpret_cast<float2*>(&out[(size_t)row * TT * HH + (size_t)t * HH + uA]) = ov;
            }
        }

        // publish h(t+1): fence covers all threads' STGs (cumulativity), then release
        __threadfence();
        __syncthreads();
        if (tid == 0) strel(myflag, (unsigned)t + 2u);
    }
}

// ---------------- launcher ----------------
extern "C" void kernel_launch(void* const* d_in, const int* in_sizes, int n_in,
                              void* d_out, int out_size) {
    const float* x_dyn    = (const float*)d_in[0];
    const float* x_static = (const float*)d_in[1];
    const float* Wx       = (const float*)d_in[2];
    const float* Wh       = (const float*)d_in[3];
    const float* bias     = (const float*)d_in[4];
    const float* sk       = (const float*)d_in[5];
    const float* sb       = (const float*)d_in[6];
    float* out = (float*)d_out;

    cudaFuncSetAttribute(lstm_persist, cudaFuncAttributeMaxDynamicSharedMemorySize, SMEM_TOTAL);

    reset_flags<<<16, 256>>>();
    prep_weights<<<K3, 128>>>(Wx, Wh);
    prep_x<<<(BB * TT * DD + 127) / 128, 128>>>(x_dyn);
    lstm_persist<<<NBLK, 256, SMEM_TOTAL>>>(x_static, sk, sb, bias, out);
}

// round 10
// speedup vs baseline: 1.4573x; 1.4573x over previous
#include <cuda_runtime.h>
#include <cuda_bf16.h>
#include <math.h>
#include <stdint.h>

#define BB   256
#define TT   365
#define HH   512
#define DD   32
#define K3   1536
#define DS   27
#define NBLK 128
#define KTOT 544

// ---------------- persistent device state ----------------
// Weight staging: row P = nt*96 + g*32 + ul, k in [0,544) = [x(32) ; h(512)]
__device__ __align__(16) __nv_bfloat16 g_Wp_hi[K3 * KTOT];
__device__ __align__(16) __nv_bfloat16 g_Wp_lo[K3 * KTOT];
__device__ __align__(16) __nv_bfloat16 g_x_hi[BB * TT * DD];
__device__ __align__(16) __nv_bfloat16 g_x_lo[BB * TT * DD];
__device__ __align__(16) __nv_bfloat16 g_h_hi[2][BB * HH];
__device__ __align__(16) __nv_bfloat16 g_h_lo[2][BB * HH];
__device__ unsigned g_grp_cnt[8 * 32];      // 128B stride per mt-group
__device__ unsigned g_grp_phase[8 * 32];

__device__ __forceinline__ float hsig(float x) {
    return fminf(fmaxf(0.2f * x + 0.5f, 0.0f), 1.0f);
}
__device__ __forceinline__ float ftanh(float x) {
    float t = __expf(-2.0f * fabsf(x));
    return copysignf(__fdividef(1.0f - t, 1.0f + t), x);
}
__device__ __forceinline__ uint32_t smem_u32(const void* p) {
    uint32_t a;
    asm("{ .reg .u64 t; cvta.to.shared.u64 t, %1; cvt.u32.u64 %0, t; }" : "=r"(a) : "l"(p));
    return a;
}

#define LDSM_X4(r0, r1, r2, r3, addr)                                          \
    asm volatile("ldmatrix.sync.aligned.m8n8.x4.shared.b16 {%0,%1,%2,%3}, [%4];" \
                 : "=r"(r0), "=r"(r1), "=r"(r2), "=r"(r3) : "r"(addr))

#define MMA_BF16(d, a0, a1, a2, a3, b0, b1)                                    \
    asm volatile("mma.sync.aligned.m16n8k16.row.col.f32.bf16.bf16.f32 "        \
                 "{%0,%1,%2,%3}, {%4,%5,%6,%7}, {%8,%9}, {%0,%1,%2,%3};"       \
                 : "+f"((d)[0]), "+f"((d)[1]), "+f"((d)[2]), "+f"((d)[3])      \
                 : "r"(a0), "r"(a1), "r"(a2), "r"(a3), "r"(b0), "r"(b1))

#define CP_ASYNC(dst, src, sz) \
    asm volatile("cp.async.cg.shared.global [%0], [%1], 16, %2;" \
                 :: "r"(dst), "l"(src), "r"(sz))
#define CP_COMMIT() asm volatile("cp.async.commit_group;" ::: "memory")
#define CP_WAIT0()  asm volatile("cp.async.wait_group 0;" ::: "memory")
#define CP_WAIT1()  asm volatile("cp.async.wait_group 1;" ::: "memory")

// ---------------- SMEM layout ----------------
#define BROW      1104            // 544*2 + 16B pad
#define SM_BHI    0
#define SM_BLO    105984
#define SM_A      211968          // 2 bufs x (hi 4608 + lo 4608); red area 12288
#define ABUF_SZ   9216
#define SMEM_TOTAL 230400

// ---------------- prep kernels ----------------
__global__ void reset_bar() {
    if (threadIdx.x < 8 * 32) {
        g_grp_cnt[threadIdx.x] = 0;
        g_grp_phase[threadIdx.x] = 0;
    }
}

__global__ void prep_weights(const float* __restrict__ Wx, const float* __restrict__ Wh) {
    int P = blockIdx.x;                 // P = nt*96 + g*32 + ul
    int nt = P / 96, rq = P - nt * 96;
    int g = rq >> 5, ul = rq & 31;
    int col = g * HH + nt * 32 + ul;
    for (int k = threadIdx.x; k < KTOT; k += blockDim.x) {
        float w = (k < DD) ? Wx[(size_t)k * K3 + col]
                           : Wh[(size_t)(k - DD) * K3 + col];
        __nv_bfloat16 hi = __float2bfloat16(w);
        g_Wp_hi[(size_t)P * KTOT + k] = hi;
        g_Wp_lo[(size_t)P * KTOT + k] = __float2bfloat16(w - __bfloat162float(hi));
    }
}

__global__ void prep_x(const float* __restrict__ x_dyn) {
    int i = blockIdx.x * blockDim.x + threadIdx.x;
    if (i >= BB * TT * DD) return;
    float v = x_dyn[i];
    __nv_bfloat16 hi = __float2bfloat16(v);
    g_x_hi[i] = hi;
    g_x_lo[i] = __float2bfloat16(v - __bfloat162float(hi));
}

// ---------------- group barrier: 16 CTAs sharing mt (release/acquire) ------
__device__ __forceinline__ void grid_bar_grp(int mt, unsigned target) {
    __syncthreads();
    if (threadIdx.x == 0) {
        unsigned old;
        asm volatile("atom.add.acq_rel.gpu.global.u32 %0, [%1], 1;"
                     : "=r"(old) : "l"(&g_grp_cnt[mt * 32]) : "memory");
        if (old + 1u == target * 16u) {
            asm volatile("st.release.gpu.global.u32 [%0], %1;"
                         :: "l"(&g_grp_phase[mt * 32]), "r"(target) : "memory");
        } else {
            unsigned p;
            do {
                asm volatile("ld.acquire.gpu.global.u32 %0, [%1];"
                             : "=r"(p) : "l"(&g_grp_phase[mt * 32]) : "memory");
            } while (p < target);
        }
    }
    __syncthreads();
}

// ---------------- persistent LSTM kernel ----------------
// 128 CTAs x 256 thr. CTA tile 32 rows x 32 units (96 z-cols).
// Warp tile 32m x 8u x 3g; warps w and w+4 split k, reduced via smem.
// chunk0 = x only, prefetched before the barrier; chunks 1-8 carry 2 h-blocks.
__global__ __launch_bounds__(256, 1)
void lstm_persist(const float* __restrict__ x_static,
                  const float* __restrict__ sk,
                  const float* __restrict__ sb,
                  const float* __restrict__ bias,
                  float* __restrict__ out) {
    extern __shared__ char smem[];
    const uint32_t s0 = smem_u32(smem);
    const int tid = threadIdx.x;
    const int lane = tid & 31;
    const int wid = tid >> 5;
    const int nq = wid & 3;
    const int khalf = wid >> 2;
    const int mt = blockIdx.x & 7;
    const int nt = blockIdx.x >> 3;
    const int m0 = mt * 32;
    const int u0 = nt * 32;

    // ---- one-time: weights into SMEM ----
    for (int i = tid; i < 96 * 68; i += 256) {
        int pl = i / 68, c = i - pl * 68;
        size_t src = (size_t)(nt * 96 + pl) * KTOT + c * 8;
        *reinterpret_cast<uint4*>(smem + SM_BHI + pl * BROW + c * 16) =
            *reinterpret_cast<const uint4*>(&g_Wp_hi[src]);
        *reinterpret_cast<uint4*>(smem + SM_BLO + pl * BROW + c * 16) =
            *reinterpret_cast<const uint4*>(&g_Wp_lo[src]);
    }

    // ---- per-thread ownership (epilogue in khalf==0 warps) ----
    const int gr = m0 + (lane >> 2);
    const int uA = u0 + nq * 8 + (lane & 3) * 2;

    const float bf0 = bias[uA],          bf1 = bias[uA + 1];
    const float bg0 = bias[HH + uA],     bg1 = bias[HH + uA + 1];
    const float bo0 = bias[2 * HH + uA], bo1 = bias[2 * HH + uA + 1];

    float c_reg[8], ig_reg[8];
#pragma unroll
    for (int i = 0; i < 8; i++) c_reg[i] = 0.f;
    if (khalf == 0) {
#pragma unroll
        for (int i = 0; i < 4; i++) {
            int row = gr + i * 8;
#pragma unroll
            for (int jj = 0; jj < 2; jj++) {
                int u = uA + jj;
                float a = sb[u];
#pragma unroll
                for (int d = 0; d < DS; d++)
                    a = fmaf(x_static[row * DS + d], sk[d * HH + u], a);
                ig_reg[i * 2 + jj] = hsig(a);
            }
            __nv_bfloat162 z2; z2.x = __float2bfloat16(0.f); z2.y = z2.x;
            *reinterpret_cast<__nv_bfloat162*>(&g_h_hi[0][row * HH + uA]) = z2;
            *reinterpret_cast<__nv_bfloat162*>(&g_h_lo[0][row * HH + uA]) = z2;
        }
    }

    // ---- hoisted loader constants ----
    // h-chunk: thread handles (row rrh, q qh) for hi (n=0) and lo (n=1)
    const int rrh = tid >> 3, qh = tid & 7;
    const int sH = qh >> 2;                         // sub-block within chunk
    const uint32_t dstoH = rrh * 144 + qh * 16;     // +4608 for lo
    const uint32_t hrowH = (m0 + rrh) * HH + (qh & 3) * 8;
    // x-chunk: 128 threads hi, 128 lo; rows 32 x q 0..3
    const int halfx = tid >> 7, rrx = (tid >> 2) & 31, qqx = tid & 3;
    const uint32_t dstx = halfx * 4608 + rrx * 144 + qqx * 16;
    const __nv_bfloat16* __restrict__ xb = halfx ? g_x_lo : g_x_hi;
    const size_t xoff = (size_t)(m0 + rrx) * TT * DD + qqx * 8;

    // prologue: prefetch chunk0 (x of t=0) into buf0
    CP_ASYNC(s0 + SM_A + dstx, xb + xoff, 16);
    CP_COMMIT();

    // ---- ldmatrix lane addresses ----
    const uint32_t a_off = (lane & 15) * 144 + (lane >> 4) * 16;
    const int oct = lane >> 3, l8 = lane & 7;
    const uint32_t koff = (oct & 1) * 16;
    const int wq8 = nq * 8;
    const uint32_t bA = s0 + SM_BHI + ((oct < 2 ? wq8 : 32 + wq8) + l8) * BROW + koff;
    const uint32_t bB = (oct < 2 ? s0 + SM_BHI + (64 + wq8 + l8) * BROW
                                 : s0 + SM_BLO + (wq8 + l8) * BROW) + koff;
    const uint32_t bC = s0 + SM_BLO + ((oct < 2 ? 32 : 64) + wq8 + l8) * BROW + koff;

    unsigned bar_t = 1;

#pragma unroll 1
    for (int t = 0; t < TT; t++) {
        const int tpar = t & 1;
        const __nv_bfloat16* __restrict__ hhi = g_h_hi[tpar];
        const __nv_bfloat16* __restrict__ hlo = g_h_lo[tpar];

        grid_bar_grp(mt, bar_t++);      // all h(t) published group-wide

        float acc[3][2][4];
#pragma unroll
        for (int g = 0; g < 3; g++)
#pragma unroll
            for (int mf = 0; mf < 2; mf++)
#pragma unroll
                for (int e2 = 0; e2 < 4; e2++) acc[g][mf][e2] = 0.f;

#pragma unroll 1
        for (int i = 0; i < 9; i++) {
            if (i > 0) __syncthreads();
            if (i < 8) {
                // issue h-chunk i+1 into buf (i+1)&1; blocks (nt+2i+sH) mod 16
                const uint32_t ab = s0 + SM_A + ((i + 1) & 1) * ABUF_SZ;
                const int b = (nt + 2 * i + sH) & 15;
                const uint32_t boff = hrowH + b * 32;
                CP_ASYNC(ab + dstoH, hhi + boff, 16);
                CP_ASYNC(ab + 4608 + dstoH, hlo + boff, 16);
                CP_COMMIT();
                CP_WAIT1();
            } else {
                CP_WAIT0();
            }
            __syncthreads();

            const uint32_t Abuf = s0 + SM_A + (i & 1) * ABUF_SZ + a_off;
            uint32_t aO, bO;
            int nks;
            if (i == 0) {
                nks = 1; aO = (uint32_t)khalf * 32; bO = (uint32_t)khalf * 32;
            } else {
                nks = 2;
                const int bk = (nt + 2 * i - 2 + khalf) & 15;
                aO = (uint32_t)khalf * 64;
                bO = 64 + 64 * (uint32_t)bk;
            }

            for (int ii = 0; ii < nks; ii++) {
                const uint32_t Ab = Abuf + aO + ii * 32;
                const uint32_t Bb = bO + ii * 32;
                uint32_t ah0, ah1, ah2, ah3, ai0, ai1, ai2, ai3;
                uint32_t al0, al1, al2, al3, am0, am1, am2, am3;
                uint32_t p0, p1, p2, p3, q0, q1, q2, q3, r0, r1, r2, r3;
                LDSM_X4(ah0, ah1, ah2, ah3, Ab);
                LDSM_X4(ai0, ai1, ai2, ai3, Ab + 16 * 144);
                LDSM_X4(al0, al1, al2, al3, Ab + 4608);
                LDSM_X4(am0, am1, am2, am3, Ab + 4608 + 16 * 144);
                LDSM_X4(p0, p1, p2, p3, bA + Bb);
                LDSM_X4(q0, q1, q2, q3, bB + Bb);
                LDSM_X4(r0, r1, r2, r3, bC + Bb);
                // hi x hi
                MMA_BF16(acc[0][0], ah0, ah1, ah2, ah3, p0, p1);
                MMA_BF16(acc[0][1], ai0, ai1, ai2, ai3, p0, p1);
                MMA_BF16(acc[1][0], ah0, ah1, ah2, ah3, p2, p3);
                MMA_BF16(acc[1][1], ai0, ai1, ai2, ai3, p2, p3);
                MMA_BF16(acc[2][0], ah0, ah1, ah2, ah3, q0, q1);
                MMA_BF16(acc[2][1], ai0, ai1, ai2, ai3, q0, q1);
                // hi x lo (weight lo)
                MMA_BF16(acc[0][0], ah0, ah1, ah2, ah3, q2, q3);
                MMA_BF16(acc[0][1], ai0, ai1, ai2, ai3, q2, q3);
                MMA_BF16(acc[1][0], ah0, ah1, ah2, ah3, r0, r1);
                MMA_BF16(acc[1][1], ai0, ai1, ai2, ai3, r0, r1);
                MMA_BF16(acc[2][0], ah0, ah1, ah2, ah3, r2, r3);
                MMA_BF16(acc[2][1], ai0, ai1, ai2, ai3, r2, r3);
                // lo x hi (activation lo)
                MMA_BF16(acc[0][0], al0, al1, al2, al3, p0, p1);
                MMA_BF16(acc[0][1], am0, am1, am2, am3, p0, p1);
                MMA_BF16(acc[1][0], al0, al1, al2, al3, p2, p3);
                MMA_BF16(acc[1][1], am0, am1, am2, am3, p2, p3);
                MMA_BF16(acc[2][0], al0, al1, al2, al3, q0, q1);
                MMA_BF16(acc[2][1], am0, am1, am2, am3, q0, q1);
            }
        }

        // ---- cross-warp k reduction via smem (A area free: no prefetch yet) ----
        __syncthreads();
        float* red = reinterpret_cast<float*>(smem + SM_A);
        if (khalf == 1) {
            int s = (wid - 4) * 32 + lane;
#pragma unroll
            for (int g = 0; g < 3; g++)
#pragma unroll
                for (int mf = 0; mf < 2; mf++)
#pragma unroll
                    for (int e2 = 0; e2 < 4; e2++)
                        red[(g * 8 + mf * 4 + e2) * 128 + s] = acc[g][mf][e2];
        }
        __syncthreads();

        if (khalf == 0) {
            int s = wid * 32 + lane;
#pragma unroll
            for (int g = 0; g < 3; g++)
#pragma unroll
                for (int mf = 0; mf < 2; mf++)
#pragma unroll
                    for (int e2 = 0; e2 < 4; e2++)
                        acc[g][mf][e2] += red[(g * 8 + mf * 4 + e2) * 128 + s];

            __nv_bfloat16* __restrict__ hdst_hi = g_h_hi[tpar ^ 1];
            __nv_bfloat16* __restrict__ hdst_lo = g_h_lo[tpar ^ 1];
#pragma unroll
            for (int i = 0; i < 4; i++) {
                const int mf = i >> 1, dp = (i & 1) * 2;
                float zf0 = acc[0][mf][dp + 0] + bf0, zf1 = acc[0][mf][dp + 1] + bf1;
                float zg0 = acc[1][mf][dp + 0] + bg0, zg1 = acc[1][mf][dp + 1] + bg1;
                float zo0 = acc[2][mf][dp + 0] + bo0, zo1 = acc[2][mf][dp + 1] + bo1;
                float c0 = hsig(zf0) * c_reg[i * 2 + 0] + ig_reg[i * 2 + 0] * ftanh(zg0);
                float c1 = hsig(zf1) * c_reg[i * 2 + 1] + ig_reg[i * 2 + 1] * ftanh(zg1);
                c_reg[i * 2 + 0] = c0;
                c_reg[i * 2 + 1] = c1;
                float h0 = hsig(zo0) * ftanh(c0);
                float h1 = hsig(zo1) * ftanh(c1);
                int row = gr + i * 8;
                int idx = row * HH + uA;
                __nv_bfloat16 b0 = __float2bfloat16(h0);
                __nv_bfloat16 b1 = __float2bfloat16(h1);
                __nv_bfloat162 ph; ph.x = b0; ph.y = b1;
                *reinterpret_cast<__nv_bfloat162*>(&hdst_hi[idx]) = ph;
                __nv_bfloat162 pl;
                pl.x = __float2bfloat16(h0 - __bfloat162float(b0));
                pl.y = __float2bfloat16(h1 - __bfloat162float(b1));
                *reinterpret_cast<__nv_bfloat162*>(&hdst_lo[idx]) = pl;
                float2 ov = make_float2(h0, h1);
                *reinterpret_cast<float2*>(&out[(size_t)row * TT * HH + (size_t)t * HH + uA]) = ov;
            }
        }

        __syncthreads();                 // red reads + h writes done
        if (t + 1 < TT) {                // prefetch next step's x chunk into buf0
            CP_ASYNC(s0 + SM_A + dstx, xb + xoff + (size_t)(t + 1) * DD, 16);
            CP_COMMIT();
        }
    }
}

// ---------------- launcher ----------------
extern "C" void kernel_launch(void* const* d_in, const int* in_sizes, int n_in,
                              void* d_out, int out_size) {
    const float* x_dyn    = (const float*)d_in[0];
    const float* x_static = (const float*)d_in[1];
    const float* Wx       = (const float*)d_in[2];
    const float* Wh       = (const float*)d_in[3];
    const float* bias     = (const float*)d_in[4];
    const float* sk       = (const float*)d_in[5];
    const float* sb       = (const float*)d_in[6];
    float* out = (float*)d_out;

    cudaFuncSetAttribute(lstm_persist, cudaFuncAttributeMaxDynamicSharedMemorySize, SMEM_TOTAL);

    reset_bar<<<1, 256>>>();
    prep_weights<<<K3, 128>>>(Wx, Wh);
    prep_x<<<(BB * TT * DD + 127) / 128, 128>>>(x_dyn);
    lstm_persist<<<NBLK, 256, SMEM_TOTAL>>>(x_static, sk, sb, bias, out);
}

// round 11
// speedup vs baseline: 1.4728x; 1.0106x over previous
#include <cuda_runtime.h>
#include <cuda_bf16.h>
#include <math.h>
#include <stdint.h>

#define BB   256
#define TT   365
#define HH   512
#define DD   32
#define K3   1536
#define DS   27
#define NBLK 128
#define KTOT 544

// ---------------- persistent device state ----------------
// Weight staging: row P = nt*96 + g*32 + ul, k in [0,544) = [x(32) ; h(512)]
__device__ __align__(16) __nv_bfloat16 g_Wp_hi[K3 * KTOT];
__device__ __align__(16) __nv_bfloat16 g_Wp_lo[K3 * KTOT];
__device__ __align__(16) __nv_bfloat16 g_x_hi[BB * TT * DD];
__device__ __align__(16) __nv_bfloat16 g_x_lo[BB * TT * DD];
__device__ __align__(16) __nv_bfloat16 g_h_hi[2][BB * HH];
__device__ __align__(16) __nv_bfloat16 g_h_lo[2][BB * HH];
__device__ unsigned g_grp_cnt[8 * 32];      // 128B stride per mt-group
__device__ unsigned g_grp_phase[8 * 32];

__device__ __forceinline__ float hsig(float x) {
    return fminf(fmaxf(0.2f * x + 0.5f, 0.0f), 1.0f);
}
__device__ __forceinline__ float ftanh(float x) {
    float t = __expf(-2.0f * fabsf(x));
    return copysignf(__fdividef(1.0f - t, 1.0f + t), x);
}
__device__ __forceinline__ uint32_t smem_u32(const void* p) {
    uint32_t a;
    asm("{ .reg .u64 t; cvta.to.shared.u64 t, %1; cvt.u32.u64 %0, t; }" : "=r"(a) : "l"(p));
    return a;
}

#define LDSM_X4(r0, r1, r2, r3, addr)                                          \
    asm volatile("ldmatrix.sync.aligned.m8n8.x4.shared.b16 {%0,%1,%2,%3}, [%4];" \
                 : "=r"(r0), "=r"(r1), "=r"(r2), "=r"(r3) : "r"(addr))

#define MMA_BF16(d, a0, a1, a2, a3, b0, b1)                                    \
    asm volatile("mma.sync.aligned.m16n8k16.row.col.f32.bf16.bf16.f32 "        \
                 "{%0,%1,%2,%3}, {%4,%5,%6,%7}, {%8,%9}, {%0,%1,%2,%3};"       \
                 : "+f"((d)[0]), "+f"((d)[1]), "+f"((d)[2]), "+f"((d)[3])      \
                 : "r"(a0), "r"(a1), "r"(a2), "r"(a3), "r"(b0), "r"(b1))

#define CP_ASYNC(dst, src, sz) \
    asm volatile("cp.async.cg.shared.global [%0], [%1], 16, %2;" \
                 :: "r"(dst), "l"(src), "r"(sz))
#define CP_COMMIT() asm volatile("cp.async.commit_group;" ::: "memory")
#define CP_WAIT0()  asm volatile("cp.async.wait_group 0;" ::: "memory")
#define CP_WAIT1()  asm volatile("cp.async.wait_group 1;" ::: "memory")
#define CP_WAIT2()  asm volatile("cp.async.wait_group 2;" ::: "memory")

// ---------------- SMEM layout ----------------
#define BROW      1104            // 544*2 + 16B pad (conflict-free LDSM phases)
#define SM_BHI    0
#define SM_BLO    105984
#define SM_A      211968          // 4 slab bufs x 4096 (swizzled); red aliases bufs 0-2
#define ABUF_SZ   4096
#define SMEM_TOTAL 228352

// ---------------- prep kernels ----------------
__global__ void reset_bar() {
    if (threadIdx.x < 8 * 32) {
        g_grp_cnt[threadIdx.x] = 0;
        g_grp_phase[threadIdx.x] = 0;
    }
}

__global__ void prep_weights(const float* __restrict__ Wx, const float* __restrict__ Wh) {
    int P = blockIdx.x;                 // P = nt*96 + g*32 + ul
    int nt = P / 96, rq = P - nt * 96;
    int g = rq >> 5, ul = rq & 31;
    int col = g * HH + nt * 32 + ul;
    for (int k = threadIdx.x; k < KTOT; k += blockDim.x) {
        float w = (k < DD) ? Wx[(size_t)k * K3 + col]
                           : Wh[(size_t)(k - DD) * K3 + col];
        __nv_bfloat16 hi = __float2bfloat16(w);
        g_Wp_hi[(size_t)P * KTOT + k] = hi;
        g_Wp_lo[(size_t)P * KTOT + k] = __float2bfloat16(w - __bfloat162float(hi));
    }
}

__global__ void prep_x(const float* __restrict__ x_dyn) {
    int i = blockIdx.x * blockDim.x + threadIdx.x;
    if (i >= BB * TT * DD) return;
    float v = x_dyn[i];
    __nv_bfloat16 hi = __float2bfloat16(v);
    g_x_hi[i] = hi;
    g_x_lo[i] = __float2bfloat16(v - __bfloat162float(hi));
}

// ---------------- group barrier: 16 CTAs sharing mt (release/acquire) ------
__device__ __forceinline__ void grid_bar_grp(int mt, unsigned target) {
    __syncthreads();
    if (threadIdx.x == 0) {
        unsigned old;
        asm volatile("atom.add.acq_rel.gpu.global.u32 %0, [%1], 1;"
                     : "=r"(old) : "l"(&g_grp_cnt[mt * 32]) : "memory");
        if (old + 1u == target * 16u) {
            asm volatile("st.release.gpu.global.u32 [%0], %1;"
                         :: "l"(&g_grp_phase[mt * 32]), "r"(target) : "memory");
        } else {
            unsigned p;
            do {
                asm volatile("ld.acquire.gpu.global.u32 %0, [%1];"
                             : "=r"(p) : "l"(&g_grp_phase[mt * 32]) : "memory");
            } while (p < target);
        }
    }
    __syncthreads();
}

// ---------------- persistent LSTM kernel ----------------
// 128 CTAs x 256 thr. CTA tile 32 rows x 32 units (96 z-cols).
// K split into 17 slabs of 32 (slab0 = x, slab j = h-block (nt+j-1)&15).
// 4 slab buffers, depth-3 cp.async pipeline, one syncthreads per slab.
// Warps: 4 unit-spans x 2 khalf (ks within slab); k-reduced via smem.
__global__ __launch_bounds__(256, 1)
void lstm_persist(const float* __restrict__ x_static,
                  const float* __restrict__ sk,
                  const float* __restrict__ sb,
                  const float* __restrict__ bias,
                  float* __restrict__ out) {
    extern __shared__ char smem[];
    const uint32_t s0 = smem_u32(smem);
    const int tid = threadIdx.x;
    const int lane = tid & 31;
    const int wid = tid >> 5;
    const int nq = wid & 3;
    const int khalf = wid >> 2;
    const int mt = blockIdx.x & 7;
    const int nt = blockIdx.x >> 3;
    const int m0 = mt * 32;
    const int u0 = nt * 32;

    // ---- one-time: weights into SMEM ----
    for (int i = tid; i < 96 * 68; i += 256) {
        int pl = i / 68, c = i - pl * 68;
        size_t src = (size_t)(nt * 96 + pl) * KTOT + c * 8;
        *reinterpret_cast<uint4*>(smem + SM_BHI + pl * BROW + c * 16) =
            *reinterpret_cast<const uint4*>(&g_Wp_hi[src]);
        *reinterpret_cast<uint4*>(smem + SM_BLO + pl * BROW + c * 16) =
            *reinterpret_cast<const uint4*>(&g_Wp_lo[src]);
    }

    // ---- per-thread ownership (epilogue in khalf==0 warps) ----
    const int gr = m0 + (lane >> 2);
    const int uA = u0 + nq * 8 + (lane & 3) * 2;

    const float bf0 = bias[uA],          bf1 = bias[uA + 1];
    const float bg0 = bias[HH + uA],     bg1 = bias[HH + uA + 1];
    const float bo0 = bias[2 * HH + uA], bo1 = bias[2 * HH + uA + 1];

    float c_reg[8], ig_reg[8];
#pragma unroll
    for (int i = 0; i < 8; i++) c_reg[i] = 0.f;
    if (khalf == 0) {
#pragma unroll
        for (int i = 0; i < 4; i++) {
            int row = gr + i * 8;
#pragma unroll
            for (int jj = 0; jj < 2; jj++) {
                int u = uA + jj;
                float a = sb[u];
#pragma unroll
                for (int d = 0; d < DS; d++)
                    a = fmaf(x_static[row * DS + d], sk[d * HH + u], a);
                ig_reg[i * 2 + jj] = hsig(a);
            }
            __nv_bfloat162 z2; z2.x = __float2bfloat16(0.f); z2.y = z2.x;
            *reinterpret_cast<__nv_bfloat162*>(&g_h_hi[0][row * HH + uA]) = z2;
            *reinterpret_cast<__nv_bfloat162*>(&g_h_lo[0][row * HH + uA]) = z2;
        }
    }

    // ---- hoisted loader constants (1 cp.async per thread per slab) ----
    const int halfl = tid >> 7;                 // 0 hi, 1 lo
    const int rowl = (tid >> 2) & 31;
    const int ql = tid & 3;
    const uint32_t dst_off = halfl * 2048 + rowl * 64
                           + ((ql ^ ((rowl >> 1) & 3)) << 4);     // XOR swizzle
    const __nv_bfloat16* __restrict__ xb = halfl ? g_x_lo : g_x_hi;
    const size_t xsrc0 = (size_t)(m0 + rowl) * TT * DD + ql * 8;
    const uint32_t hrow = (m0 + rowl) * HH + ql * 8;              // + b*32

    // ---- ldmatrix lane addresses ----
    // A: swizzled 64B rows; cfull = khalf*2 + colhalf, s = ((lane&15)>>1)&3
    const uint32_t a_off = (lane & 15) * 64
        + ((((uint32_t)khalf * 2 + (lane >> 4)) ^ (((lane & 15) >> 1) & 3)) << 4);
    const int oct = lane >> 3, l8 = lane & 7;
    const uint32_t koff = (oct & 1) * 16;
    const int wq8 = nq * 8;
    const uint32_t bA = s0 + SM_BHI + ((oct < 2 ? wq8 : 32 + wq8) + l8) * BROW + koff;
    const uint32_t bB = (oct < 2 ? s0 + SM_BHI + (64 + wq8 + l8) * BROW
                                 : s0 + SM_BLO + (wq8 + l8) * BROW) + koff;
    const uint32_t bC = s0 + SM_BLO + ((oct < 2 ? 32 : 64) + wq8 + l8) * BROW + koff;

    // prologue: h(0) visible within CTA, then issue slab0 (x) + slab1 (own h)
    __syncthreads();
    CP_ASYNC(s0 + SM_A + dst_off, xb + xsrc0, 16);
    CP_COMMIT();
    {
        const __nv_bfloat16* hb = halfl ? g_h_lo[0] : g_h_hi[0];
        CP_ASYNC(s0 + SM_A + ABUF_SZ + dst_off, hb + hrow + nt * 32, 16);
        CP_COMMIT();
    }

    unsigned bar_t = 1;

#pragma unroll 1
    for (int t = 0; t < TT; t++) {
        const int tpar = t & 1;
        const __nv_bfloat16* __restrict__ hsrc =
            halfl ? g_h_lo[tpar] : g_h_hi[tpar];

        grid_bar_grp(mt, bar_t++);      // all h(t) published group-wide

        // issue slab 2 (block (nt+1)&15)
        CP_ASYNC(s0 + SM_A + 2 * ABUF_SZ + dst_off,
                 hsrc + hrow + (((nt + 1) & 15) << 5), 16);
        CP_COMMIT();

        float acc[3][2][4];
#pragma unroll
        for (int g = 0; g < 3; g++)
#pragma unroll
            for (int mf = 0; mf < 2; mf++)
#pragma unroll
                for (int e2 = 0; e2 < 4; e2++) acc[g][mf][e2] = 0.f;

#pragma unroll 1
        for (int j = 0; j < 17; j++) {
            if (j < 15)      CP_WAIT2();    // slab j landed
            else if (j == 15) CP_WAIT1();
            else              CP_WAIT0();
            __syncthreads();                // buf (j+3)&3 = (j-1)&3 free, slab j visible
            if (j <= 13) {                  // issue slab j+3 (block (nt+j+2)&15)
                CP_ASYNC(s0 + SM_A + ((j + 3) & 3) * ABUF_SZ + dst_off,
                         hsrc + hrow + (((nt + j + 2) & 15) << 5), 16);
                CP_COMMIT();
            }

            const uint32_t Ab = s0 + SM_A + (j & 3) * ABUF_SZ + a_off;
            const uint32_t Bb = (j == 0)
                ? (uint32_t)(khalf * 32)
                : (uint32_t)(64 + 64 * ((nt + j - 1) & 15) + khalf * 32);

            uint32_t ah0, ah1, ah2, ah3, ai0, ai1, ai2, ai3;
            uint32_t al0, al1, al2, al3, am0, am1, am2, am3;
            uint32_t p0, p1, p2, p3, q0, q1, q2, q3, r0, r1, r2, r3;
            LDSM_X4(ah0, ah1, ah2, ah3, Ab);
            LDSM_X4(ai0, ai1, ai2, ai3, Ab + 1024);
            LDSM_X4(al0, al1, al2, al3, Ab + 2048);
            LDSM_X4(am0, am1, am2, am3, Ab + 3072);
            LDSM_X4(p0, p1, p2, p3, bA + Bb);
            LDSM_X4(q0, q1, q2, q3, bB + Bb);
            LDSM_X4(r0, r1, r2, r3, bC + Bb);
            // hi x hi
            MMA_BF16(acc[0][0], ah0, ah1, ah2, ah3, p0, p1);
            MMA_BF16(acc[0][1], ai0, ai1, ai2, ai3, p0, p1);
            MMA_BF16(acc[1][0], ah0, ah1, ah2, ah3, p2, p3);
            MMA_BF16(acc[1][1], ai0, ai1, ai2, ai3, p2, p3);
            MMA_BF16(acc[2][0], ah0, ah1, ah2, ah3, q0, q1);
            MMA_BF16(acc[2][1], ai0, ai1, ai2, ai3, q0, q1);
            // hi x lo (weight lo)
            MMA_BF16(acc[0][0], ah0, ah1, ah2, ah3, q2, q3);
            MMA_BF16(acc[0][1], ai0, ai1, ai2, ai3, q2, q3);
            MMA_BF16(acc[1][0], ah0, ah1, ah2, ah3, r0, r1);
            MMA_BF16(acc[1][1], ai0, ai1, ai2, ai3, r0, r1);
            MMA_BF16(acc[2][0], ah0, ah1, ah2, ah3, r2, r3);
            MMA_BF16(acc[2][1], ai0, ai1, ai2, ai3, r2, r3);
            // lo x hi (activation lo)
            MMA_BF16(acc[0][0], al0, al1, al2, al3, p0, p1);
            MMA_BF16(acc[0][1], am0, am1, am2, am3, p0, p1);
            MMA_BF16(acc[1][0], al0, al1, al2, al3, p2, p3);
            MMA_BF16(acc[1][1], am0, am1, am2, am3, p2, p3);
            MMA_BF16(acc[2][0], al0, al1, al2, al3, q0, q1);
            MMA_BF16(acc[2][1], am0, am1, am2, am3, q0, q1);
        }

        // ---- cross-warp k reduction via smem (aliases slab bufs 0-2) ----
        __syncthreads();
        float* red = reinterpret_cast<float*>(smem + SM_A);
        if (khalf == 1) {
            int s = (wid - 4) * 32 + lane;
#pragma unroll
            for (int g = 0; g < 3; g++)
#pragma unroll
                for (int mf = 0; mf < 2; mf++)
#pragma unroll
                    for (int e2 = 0; e2 < 4; e2++)
                        red[(g * 8 + mf * 4 + e2) * 128 + s] = acc[g][mf][e2];
        }
        __syncthreads();

        if (khalf == 0) {
            int s = wid * 32 + lane;
#pragma unroll
            for (int g = 0; g < 3; g++)
#pragma unroll
                for (int mf = 0; mf < 2; mf++)
#pragma unroll
                    for (int e2 = 0; e2 < 4; e2++)
                        acc[g][mf][e2] += red[(g * 8 + mf * 4 + e2) * 128 + s];

            __nv_bfloat16* __restrict__ hdst_hi = g_h_hi[tpar ^ 1];
            __nv_bfloat16* __restrict__ hdst_lo = g_h_lo[tpar ^ 1];
#pragma unroll
            for (int i = 0; i < 4; i++) {
                const int mf = i >> 1, dp = (i & 1) * 2;
                float zf0 = acc[0][mf][dp + 0] + bf0, zf1 = acc[0][mf][dp + 1] + bf1;
                float zg0 = acc[1][mf][dp + 0] + bg0, zg1 = acc[1][mf][dp + 1] + bg1;
                float zo0 = acc[2][mf][dp + 0] + bo0, zo1 = acc[2][mf][dp + 1] + bo1;
                float c0 = hsig(zf0) * c_reg[i * 2 + 0] + ig_reg[i * 2 + 0] * ftanh(zg0);
                float c1 = hsig(zf1) * c_reg[i * 2 + 1] + ig_reg[i * 2 + 1] * ftanh(zg1);
                c_reg[i * 2 + 0] = c0;
                c_reg[i * 2 + 1] = c1;
                float h0 = hsig(zo0) * ftanh(c0);
                float h1 = hsig(zo1) * ftanh(c1);
                int row = gr + i * 8;
                int idx = row * HH + uA;
                __nv_bfloat16 b0 = __float2bfloat16(h0);
                __nv_bfloat16 b1 = __float2bfloat16(h1);
                __nv_bfloat162 ph; ph.x = b0; ph.y = b1;
                *reinterpret_cast<__nv_bfloat162*>(&hdst_hi[idx]) = ph;
                __nv_bfloat162 pl;
                pl.x = __float2bfloat16(h0 - __bfloat162float(b0));
                pl.y = __float2bfloat16(h1 - __bfloat162float(b1));
                *reinterpret_cast<__nv_bfloat162*>(&hdst_lo[idx]) = pl;
                float2 ov = make_float2(h0, h1);
                *reinterpret_cast<float2*>(&out[(size_t)row * TT * HH + (size_t)t * HH + uA]) = ov;
            }
        }

        __syncthreads();                 // red reads + h(t+1) writes done CTA-wide
        if (t + 1 < TT) {                // issue next step's slab0 (x) + slab1 (own h)
            CP_ASYNC(s0 + SM_A + dst_off, xb + xsrc0 + (size_t)(t + 1) * DD, 16);
            CP_COMMIT();
            const __nv_bfloat16* hb =
                halfl ? g_h_lo[(t + 1) & 1] : g_h_hi[(t + 1) & 1];
            CP_ASYNC(s0 + SM_A + ABUF_SZ + dst_off, hb + hrow + nt * 32, 16);
            CP_COMMIT();
        }
    }
}

// ---------------- launcher ----------------
extern "C" void kernel_launch(void* const* d_in, const int* in_sizes, int n_in,
                              void* d_out, int out_size) {
    const float* x_dyn    = (const float*)d_in[0];
    const float* x_static = (const float*)d_in[1];
    const float* Wx       = (const float*)d_in[2];
    const float* Wh       = (const float*)d_in[3];
    const float* bias     = (const float*)d_in[4];
    const float* sk       = (const float*)d_in[5];
    const float* sb       = (const float*)d_in[6];
    float* out = (float*)d_out;

    cudaFuncSetAttribute(lstm_persist, cudaFuncAttributeMaxDynamicSharedMemorySize, SMEM_TOTAL);

    reset_bar<<<1, 256>>>();
    prep_weights<<<K3, 128>>>(Wx, Wh);
    prep_x<<<(BB * TT * DD + 127) / 128, 128>>>(x_dyn);
    lstm_persist<<<NBLK, 256, SMEM_TOTAL>>>(x_static, sk, sb, bias, out);
}

// round 12
// speedup vs baseline: 1.7489x; 1.1875x over previous
#include <cuda_runtime.h>
#include <cuda_bf16.h>
#include <math.h>
#include <stdint.h>

#define BB   256
#define TT   365
#define HH   512
#define DD   32
#define K3   1536
#define DS   27
#define NBLK 128
#define KTOT 544

// ---------------- persistent device state ----------------
// Weight staging: row P = nt*96 + g*32 + ul, k in [0,544) = [x(32) ; h(512)]
__device__ __align__(16) __nv_bfloat16 g_Wp_hi[K3 * KTOT];
__device__ __align__(16) __nv_bfloat16 g_Wp_lo[K3 * KTOT];
__device__ __align__(16) __nv_bfloat16 g_x_hi[BB * TT * DD];
__device__ __align__(16) __nv_bfloat16 g_x_lo[BB * TT * DD];
__device__ __align__(16) __nv_bfloat16 g_h_hi[2][BB * HH];
__device__ __align__(16) __nv_bfloat16 g_h_lo[2][BB * HH];
__device__ unsigned g_grp_cnt[8 * 32];      // 128B stride per mt-group
__device__ unsigned g_grp_phase[8 * 32];

__device__ __forceinline__ float hsig(float x) {
    return fminf(fmaxf(0.2f * x + 0.5f, 0.0f), 1.0f);
}
__device__ __forceinline__ float ftanh(float x) {
    float t = __expf(-2.0f * fabsf(x));
    return copysignf(__fdividef(1.0f - t, 1.0f + t), x);
}
__device__ __forceinline__ uint32_t smem_u32(const void* p) {
    uint32_t a;
    asm("{ .reg .u64 t; cvta.to.shared.u64 t, %1; cvt.u32.u64 %0, t; }" : "=r"(a) : "l"(p));
    return a;
}

#define LDSM_X4(r0, r1, r2, r3, addr)                                          \
    asm volatile("ldmatrix.sync.aligned.m8n8.x4.shared.b16 {%0,%1,%2,%3}, [%4];" \
                 : "=r"(r0), "=r"(r1), "=r"(r2), "=r"(r3) : "r"(addr))

#define MMA_BF16(d, a0, a1, a2, a3, b0, b1)                                    \
    asm volatile("mma.sync.aligned.m16n8k16.row.col.f32.bf16.bf16.f32 "        \
                 "{%0,%1,%2,%3}, {%4,%5,%6,%7}, {%8,%9}, {%0,%1,%2,%3};"       \
                 : "+f"((d)[0]), "+f"((d)[1]), "+f"((d)[2]), "+f"((d)[3])      \
                 : "r"(a0), "r"(a1), "r"(a2), "r"(a3), "r"(b0), "r"(b1))

#define CP_ASYNC(dst, src, sz) \
    asm volatile("cp.async.cg.shared.global [%0], [%1], 16, %2;" \
                 :: "r"(dst), "l"(src), "r"(sz))
#define CP_COMMIT() asm volatile("cp.async.commit_group;" ::: "memory")
#define CP_WAIT0()  asm volatile("cp.async.wait_group 0;" ::: "memory")
#define CP_WAIT1()  asm volatile("cp.async.wait_group 1;" ::: "memory")
#define CP_WAIT2()  asm volatile("cp.async.wait_group 2;" ::: "memory")
#define CP_WAIT3()  asm volatile("cp.async.wait_group 3;" ::: "memory")

// ---------------- SMEM layout ----------------
#define BROW      1104            // 544*2 + 16B pad
#define SM_BHI    0
#define SM_BLO    105984
#define SM_A      211968          // 4 slab bufs x 4096 (swizzled); red aliases bufs 0-2
#define ABUF_SZ   4096
#define SMEM_TOTAL 228352

// ---------------- prep kernels ----------------
__global__ void reset_bar() {
    if (threadIdx.x < 8 * 32) {
        g_grp_cnt[threadIdx.x] = 0;
        g_grp_phase[threadIdx.x] = 0;
    }
}

__global__ void prep_weights(const float* __restrict__ Wx, const float* __restrict__ Wh) {
    int P = blockIdx.x;                 // P = nt*96 + g*32 + ul
    int nt = P / 96, rq = P - nt * 96;
    int g = rq >> 5, ul = rq & 31;
    int col = g * HH + nt * 32 + ul;
    for (int k = threadIdx.x; k < KTOT; k += blockDim.x) {
        float w = (k < DD) ? Wx[(size_t)k * K3 + col]
                           : Wh[(size_t)(k - DD) * K3 + col];
        __nv_bfloat16 hi = __float2bfloat16(w);
        g_Wp_hi[(size_t)P * KTOT + k] = hi;
        g_Wp_lo[(size_t)P * KTOT + k] = __float2bfloat16(w - __bfloat162float(hi));
    }
}

__global__ void prep_x(const float* __restrict__ x_dyn) {
    int i = blockIdx.x * blockDim.x + threadIdx.x;
    if (i >= BB * TT * DD) return;
    float v = x_dyn[i];
    __nv_bfloat16 hi = __float2bfloat16(v);
    g_x_hi[i] = hi;
    g_x_lo[i] = __float2bfloat16(v - __bfloat162float(hi));
}

// ---------------- group barrier: 16 CTAs sharing mt (release/acquire) ------
__device__ __forceinline__ void grid_bar_grp(int mt, unsigned target) {
    __syncthreads();
    if (threadIdx.x == 0) {
        unsigned old;
        asm volatile("atom.add.acq_rel.gpu.global.u32 %0, [%1], 1;"
                     : "=r"(old) : "l"(&g_grp_cnt[mt * 32]) : "memory");
        if (old + 1u == target * 16u) {
            asm volatile("st.release.gpu.global.u32 [%0], %1;"
                         :: "l"(&g_grp_phase[mt * 32]), "r"(target) : "memory");
        } else {
            unsigned p;
            do {
                asm volatile("ld.acquire.gpu.global.u32 %0, [%1];"
                             : "=r"(p) : "l"(&g_grp_phase[mt * 32]) : "memory");
            } while (p < target);
        }
    }
    __syncthreads();
}

// ---- fragment bank load: 4 A LDSM + 3 B LDSM ----
#define LDSM_BANK(FA, FB, Ab_, Bb_)                                            \
    LDSM_X4(FA[0], FA[1], FA[2], FA[3], (Ab_));                                \
    LDSM_X4(FA[4], FA[5], FA[6], FA[7], (Ab_) + 1024);                         \
    LDSM_X4(FA[8], FA[9], FA[10], FA[11], (Ab_) + 2048);                       \
    LDSM_X4(FA[12], FA[13], FA[14], FA[15], (Ab_) + 3072);                     \
    LDSM_X4(FB[0], FB[1], FB[2], FB[3], bA + (Bb_));                           \
    LDSM_X4(FB[4], FB[5], FB[6], FB[7], bB + (Bb_));                           \
    LDSM_X4(FB[8], FB[9], FB[10], FB[11], bC + (Bb_));

// ---- 18 compensated MMAs on one bank ----
#define MMA_BANK(FA, FB)                                                       \
    MMA_BF16(acc[0][0], FA[0], FA[1], FA[2], FA[3], FB[0], FB[1]);             \
    MMA_BF16(acc[0][1], FA[4], FA[5], FA[6], FA[7], FB[0], FB[1]);             \
    MMA_BF16(acc[1][0], FA[0], FA[1], FA[2], FA[3], FB[2], FB[3]);             \
    MMA_BF16(acc[1][1], FA[4], FA[5], FA[6], FA[7], FB[2], FB[3]);             \
    MMA_BF16(acc[2][0], FA[0], FA[1], FA[2], FA[3], FB[4], FB[5]);             \
    MMA_BF16(acc[2][1], FA[4], FA[5], FA[6], FA[7], FB[4], FB[5]);             \
    MMA_BF16(acc[0][0], FA[0], FA[1], FA[2], FA[3], FB[6], FB[7]);             \
    MMA_BF16(acc[0][1], FA[4], FA[5], FA[6], FA[7], FB[6], FB[7]);             \
    MMA_BF16(acc[1][0], FA[0], FA[1], FA[2], FA[3], FB[8], FB[9]);             \
    MMA_BF16(acc[1][1], FA[4], FA[5], FA[6], FA[7], FB[8], FB[9]);             \
    MMA_BF16(acc[2][0], FA[0], FA[1], FA[2], FA[3], FB[10], FB[11]);           \
    MMA_BF16(acc[2][1], FA[4], FA[5], FA[6], FA[7], FB[10], FB[11]);           \
    MMA_BF16(acc[0][0], FA[8], FA[9], FA[10], FA[11], FB[0], FB[1]);           \
    MMA_BF16(acc[0][1], FA[12], FA[13], FA[14], FA[15], FB[0], FB[1]);         \
    MMA_BF16(acc[1][0], FA[8], FA[9], FA[10], FA[11], FB[2], FB[3]);           \
    MMA_BF16(acc[1][1], FA[12], FA[13], FA[14], FA[15], FB[2], FB[3]);         \
    MMA_BF16(acc[2][0], FA[8], FA[9], FA[10], FA[11], FB[4], FB[5]);           \
    MMA_BF16(acc[2][1], FA[12], FA[13], FA[14], FA[15], FB[4], FB[5]);

// One pipeline iteration: wait -> sync -> issue j+4 -> LDSM j+1 -> MMA j
#define STEP_ITER(J, FAc, FBc, FAn, FBn) do {                                  \
    if ((J) <= 13) { CP_WAIT2(); }                                             \
    else if ((J) == 14) { CP_WAIT1(); }                                        \
    else if ((J) == 15) { CP_WAIT0(); }                                        \
    __syncthreads();                                                           \
    if ((J) <= 12) {                                                           \
        CP_ASYNC(s0 + SM_A + (uint32_t)(((J) + 4) & 3) * ABUF_SZ + dst_off,    \
                 hsrc + hrow + ((uint32_t)((nt + (J) + 3) & 15) << 5), 16);    \
        CP_COMMIT();                                                           \
    }                                                                          \
    if ((J) < 16) {                                                            \
        const uint32_t Ab_ = s0 + SM_A + (uint32_t)(((J) + 1) & 3) * ABUF_SZ + a_off; \
        const uint32_t Bb_ = 64 + 64 * (uint32_t)((nt + (J)) & 15) + khoff;    \
        LDSM_BANK(FAn, FBn, Ab_, Bb_)                                          \
    }                                                                          \
    MMA_BANK(FAc, FBc)                                                         \
} while (0)

// ---------------- persistent LSTM kernel ----------------
// 128 CTAs x 256 thr. CTA tile 32 rows x 32 units (96 z-cols).
// K = 17 slabs of 32 (slab0 = x, slab j = h-block (nt+j-1)&15).
// 4 slab buffers + register double-buffered fragments: MMA of slab j overlaps
// LDSM of slab j+1 and cp.async of slab j+4.
__global__ __launch_bounds__(256, 1)
void lstm_persist(const float* __restrict__ x_static,
                  const float* __restrict__ sk,
                  const float* __restrict__ sb,
                  const float* __restrict__ bias,
                  float* __restrict__ out) {
    extern __shared__ char smem[];
    const uint32_t s0 = smem_u32(smem);
    const int tid = threadIdx.x;
    const int lane = tid & 31;
    const int wid = tid >> 5;
    const int nq = wid & 3;
    const int khalf = wid >> 2;
    const uint32_t khoff = (uint32_t)khalf * 32;
    const int mt = blockIdx.x & 7;
    const int nt = blockIdx.x >> 3;
    const int m0 = mt * 32;
    const int u0 = nt * 32;

    // ---- one-time: weights into SMEM ----
    for (int i = tid; i < 96 * 68; i += 256) {
        int pl = i / 68, c = i - pl * 68;
        size_t src = (size_t)(nt * 96 + pl) * KTOT + c * 8;
        *reinterpret_cast<uint4*>(smem + SM_BHI + pl * BROW + c * 16) =
            *reinterpret_cast<const uint4*>(&g_Wp_hi[src]);
        *reinterpret_cast<uint4*>(smem + SM_BLO + pl * BROW + c * 16) =
            *reinterpret_cast<const uint4*>(&g_Wp_lo[src]);
    }

    // ---- per-thread ownership (epilogue in khalf==0 warps) ----
    const int gr = m0 + (lane >> 2);
    const int uA = u0 + nq * 8 + (lane & 3) * 2;

    const float bf0 = bias[uA],          bf1 = bias[uA + 1];
    const float bg0 = bias[HH + uA],     bg1 = bias[HH + uA + 1];
    const float bo0 = bias[2 * HH + uA], bo1 = bias[2 * HH + uA + 1];

    float c_reg[8], ig_reg[8];
#pragma unroll
    for (int i = 0; i < 8; i++) c_reg[i] = 0.f;
    if (khalf == 0) {
#pragma unroll
        for (int i = 0; i < 4; i++) {
            int row = gr + i * 8;
#pragma unroll
            for (int jj = 0; jj < 2; jj++) {
                int u = uA + jj;
                float a = sb[u];
#pragma unroll
                for (int d = 0; d < DS; d++)
                    a = fmaf(x_static[row * DS + d], sk[d * HH + u], a);
                ig_reg[i * 2 + jj] = hsig(a);
            }
            __nv_bfloat162 z2; z2.x = __float2bfloat16(0.f); z2.y = z2.x;
            *reinterpret_cast<__nv_bfloat162*>(&g_h_hi[0][row * HH + uA]) = z2;
            *reinterpret_cast<__nv_bfloat162*>(&g_h_lo[0][row * HH + uA]) = z2;
        }
    }

    // ---- hoisted loader constants (1 cp.async per thread per slab) ----
    const int halfl = tid >> 7;                 // 0 hi, 1 lo
    const int rowl = (tid >> 2) & 31;
    const int ql = tid & 3;
    const uint32_t dst_off = halfl * 2048 + rowl * 64
                           + ((ql ^ ((rowl >> 1) & 3)) << 4);     // XOR swizzle
    const __nv_bfloat16* __restrict__ xb = halfl ? g_x_lo : g_x_hi;
    const size_t xsrc0 = (size_t)(m0 + rowl) * TT * DD + ql * 8;
    const uint32_t hrow = (m0 + rowl) * HH + ql * 8;              // + b*32

    // ---- ldmatrix lane addresses ----
    const uint32_t a_off = (lane & 15) * 64
        + ((((uint32_t)khalf * 2 + (lane >> 4)) ^ (((lane & 15) >> 1) & 3)) << 4);
    const int oct = lane >> 3, l8 = lane & 7;
    const uint32_t koff = (oct & 1) * 16;
    const int wq8 = nq * 8;
    const uint32_t bA = s0 + SM_BHI + ((oct < 2 ? wq8 : 32 + wq8) + l8) * BROW + koff;
    const uint32_t bB = (oct < 2 ? s0 + SM_BHI + (64 + wq8 + l8) * BROW
                                 : s0 + SM_BLO + (wq8 + l8) * BROW) + koff;
    const uint32_t bC = s0 + SM_BLO + ((oct < 2 ? 32 : 64) + wq8 + l8) * BROW + koff;

    // prologue: h(0) visible within CTA, then issue slab0 (x) + slab1 (own h)
    __syncthreads();
    CP_ASYNC(s0 + SM_A + dst_off, xb + xsrc0, 16);
    CP_COMMIT();
    {
        const __nv_bfloat16* hb = halfl ? g_h_lo[0] : g_h_hi[0];
        CP_ASYNC(s0 + SM_A + ABUF_SZ + dst_off, hb + hrow + nt * 32, 16);
        CP_COMMIT();
    }

    unsigned bar_t = 1;
    uint32_t fA0[16], fB0[12], fA1[16], fB1[12];

#pragma unroll 1
    for (int t = 0; t < TT; t++) {
        const int tpar = t & 1;
        const __nv_bfloat16* __restrict__ hsrc =
            halfl ? g_h_lo[tpar] : g_h_hi[tpar];

        grid_bar_grp(mt, bar_t++);      // all h(t) published group-wide

        // issue slab2 (block (nt+1)&15) and slab3 (block (nt+2)&15)
        CP_ASYNC(s0 + SM_A + 2 * ABUF_SZ + dst_off,
                 hsrc + hrow + (((nt + 1) & 15) << 5), 16);
        CP_COMMIT();
        CP_ASYNC(s0 + SM_A + 3 * ABUF_SZ + dst_off,
                 hsrc + hrow + (((nt + 2) & 15) << 5), 16);
        CP_COMMIT();

        float acc[3][2][4];
#pragma unroll
        for (int g = 0; g < 3; g++)
#pragma unroll
            for (int mf = 0; mf < 2; mf++)
#pragma unroll
                for (int e2 = 0; e2 < 4; e2++) acc[g][mf][e2] = 0.f;

        // preload bank0 <- slab0 (x)
        CP_WAIT3();
        __syncthreads();
        {
            const uint32_t Ab_ = s0 + SM_A + a_off;
            LDSM_BANK(fA0, fB0, Ab_, khoff)
        }

#pragma unroll 1
        for (int j = 0; j < 16; j += 2) {
            STEP_ITER(j,     fA0, fB0, fA1, fB1);
            STEP_ITER(j + 1, fA1, fB1, fA0, fB0);
        }
        STEP_ITER(16, fA0, fB0, fA1, fB1);

        // ---- cross-warp k reduction via smem (aliases slab bufs 0-2) ----
        __syncthreads();
        float* red = reinterpret_cast<float*>(smem + SM_A);
        if (khalf == 1) {
            int s = (wid - 4) * 32 + lane;
#pragma unroll
            for (int g = 0; g < 3; g++)
#pragma unroll
                for (int mf = 0; mf < 2; mf++)
#pragma unroll
                    for (int e2 = 0; e2 < 4; e2++)
                        red[(g * 8 + mf * 4 + e2) * 128 + s] = acc[g][mf][e2];
        }
        __syncthreads();

        if (khalf == 0) {
            int s = wid * 32 + lane;
#pragma unroll
            for (int g = 0; g < 3; g++)
#pragma unroll
                for (int mf = 0; mf < 2; mf++)
#pragma unroll
                    for (int e2 = 0; e2 < 4; e2++)
                        acc[g][mf][e2] += red[(g * 8 + mf * 4 + e2) * 128 + s];

            __nv_bfloat16* __restrict__ hdst_hi = g_h_hi[tpar ^ 1];
            __nv_bfloat16* __restrict__ hdst_lo = g_h_lo[tpar ^ 1];
#pragma unroll
            for (int i = 0; i < 4; i++) {
                const int mf = i >> 1, dp = (i & 1) * 2;
                float zf0 = acc[0][mf][dp + 0] + bf0, zf1 = acc[0][mf][dp + 1] + bf1;
                float zg0 = acc[1][mf][dp + 0] + bg0, zg1 = acc[1][mf][dp + 1] + bg1;
                float zo0 = acc[2][mf][dp + 0] + bo0, zo1 = acc[2][mf][dp + 1] + bo1;
                float c0 = hsig(zf0) * c_reg[i * 2 + 0] + ig_reg[i * 2 + 0] * ftanh(zg0);
                float c1 = hsig(zf1) * c_reg[i * 2 + 1] + ig_reg[i * 2 + 1] * ftanh(zg1);
                c_reg[i * 2 + 0] = c0;
                c_reg[i * 2 + 1] = c1;
                float h0 = hsig(zo0) * ftanh(c0);
                float h1 = hsig(zo1) * ftanh(c1);
                int row = gr + i * 8;
                int idx = row * HH + uA;
                __nv_bfloat16 b0 = __float2bfloat16(h0);
                __nv_bfloat16 b1 = __float2bfloat16(h1);
                __nv_bfloat162 ph; ph.x = b0; ph.y = b1;
                *reinterpret_cast<__nv_bfloat162*>(&hdst_hi[idx]) = ph;
                __nv_bfloat162 pl;
                pl.x = __float2bfloat16(h0 - __bfloat162float(b0));
                pl.y = __float2bfloat16(h1 - __bfloat162float(b1));
                *reinterpret_cast<__nv_bfloat162*>(&hdst_lo[idx]) = pl;
                float2 ov = make_float2(h0, h1);
                *reinterpret_cast<float2*>(&out[(size_t)row * TT * HH + (size_t)t * HH + uA]) = ov;
            }
        }

        __syncthreads();                 // red reads + h(t+1) writes done CTA-wide
        if (t + 1 < TT) {                // issue next step's slab0 (x) + slab1 (own h)
            CP_ASYNC(s0 + SM_A + dst_off, xb + xsrc0 + (size_t)(t + 1) * DD, 16);
            CP_COMMIT();
            const __nv_bfloat16* hb =
                halfl ? g_h_lo[(t + 1) & 1] : g_h_hi[(t + 1) & 1];
            CP_ASYNC(s0 + SM_A + ABUF_SZ + dst_off, hb + hrow + nt * 32, 16);
            CP_COMMIT();
        }
    }
}

// ---------------- launcher ----------------
extern "C" void kernel_launch(void* const* d_in, const int* in_sizes, int n_in,
                              void* d_out, int out_size) {
    const float* x_dyn    = (const float*)d_in[0];
    const float* x_static = (const float*)d_in[1];
    const float* Wx       = (const float*)d_in[2];
    const float* Wh       = (const float*)d_in[3];
    const float* bias     = (const float*)d_in[4];
    const float* sk       = (const float*)d_in[5];
    const float* sb       = (const float*)d_in[6];
    float* out = (float*)d_out;

    cudaFuncSetAttribute(lstm_persist, cudaFuncAttributeMaxDynamicSharedMemorySize, SMEM_TOTAL);

    reset_bar<<<1, 256>>>();
    prep_weights<<<K3, 128>>>(Wx, Wh);
    prep_x<<<(BB * TT * DD + 127) / 128, 128>>>(x_dyn);
    lstm_persist<<<NBLK, 256, SMEM_TOTAL>>>(x_static, sk, sb, bias, out);
}